// round 2
// baseline (speedup 1.0000x reference)
#include <cuda_runtime.h>
#include <math.h>

// Problem dims
#define BQ    4
#define SQ    8192
#define DQ    2048      // input feature dim
#define RQ    1024      // RKHS
#define MQ    128       // EMB
#define EQ    64        // experts
#define TQ    32768     // tokens = B*S

// Scratch (no allocation allowed -> __device__ globals)
__device__ float g_remb[EQ * RQ];    // rkhs_emb[e][r]
__device__ float g_wcomb[DQ * EQ];   // W_comb[d][e]
__device__ float g_bias[EQ];         // bias_comb[e]

// ---------------------------------------------------------------------------
// K1: rkhs_emb[e][r] = sum_m emb[e][m] * W_exp[r][m] + b_exp[r]
// grid (RQ/256, EQ), 256 threads
// ---------------------------------------------------------------------------
__global__ void k1_remb(const float* __restrict__ W_exp,
                        const float* __restrict__ b_exp,
                        const float* __restrict__ emb) {
    __shared__ float s_emb[MQ];
    const int e = blockIdx.y;
    const int r = blockIdx.x * 256 + threadIdx.x;
    if (threadIdx.x < MQ) s_emb[threadIdx.x] = emb[e * MQ + threadIdx.x];
    __syncthreads();
    const float4* w4 = reinterpret_cast<const float4*>(W_exp) + r * (MQ / 4);
    const float4* x4 = reinterpret_cast<const float4*>(s_emb);
    float acc = b_exp[r];
#pragma unroll
    for (int m = 0; m < MQ / 4; m++) {
        float4 w = w4[m];
        float4 x = x4[m];
        acc += w.x * x.x + w.y * x.y + w.z * x.z + w.w * x.w;
    }
    g_remb[e * RQ + r] = acc;
}

// ---------------------------------------------------------------------------
// K2: W_comb[d][e] = sum_r W_hid[r][d] * rkhs_emb[e][r]
// grid (DQ/256, EQ/8), 256 threads; each thread: 1 d x 8 e
// W_hid reads are coalesced (consecutive d across the warp at fixed r).
// ---------------------------------------------------------------------------
__global__ void k2_wcomb(const float* __restrict__ W_hid) {
    __shared__ float s_r[8 * RQ];            // 8 experts x 1024 r = 32 KB
    const int d  = blockIdx.x * 256 + threadIdx.x;
    const int e0 = blockIdx.y * 8;
    {
        const float4* src = reinterpret_cast<const float4*>(g_remb + e0 * RQ);
        float4* dst = reinterpret_cast<float4*>(s_r);
#pragma unroll
        for (int i = 0; i < 8; i++) dst[threadIdx.x + i * 256] = src[threadIdx.x + i * 256];
    }
    __syncthreads();

    float acc[8];
#pragma unroll
    for (int j = 0; j < 8; j++) acc[j] = 0.f;

    for (int r = 0; r < RQ; r += 4) {
        float w0 = W_hid[(r + 0) * DQ + d];
        float w1 = W_hid[(r + 1) * DQ + d];
        float w2 = W_hid[(r + 2) * DQ + d];
        float w3 = W_hid[(r + 3) * DQ + d];
#pragma unroll
        for (int j = 0; j < 8; j++) {
            float4 rr = *reinterpret_cast<const float4*>(&s_r[j * RQ + r]);
            acc[j] += w0 * rr.x + w1 * rr.y + w2 * rr.z + w3 * rr.w;
        }
    }
#pragma unroll
    for (int j = 0; j < 8; j++) g_wcomb[d * EQ + e0 + j] = acc[j];
}

// ---------------------------------------------------------------------------
// K2b: bias_comb[e] = sum_r b_hid[r] * rkhs_emb[e][r]   (1 block, 64 threads)
// ---------------------------------------------------------------------------
__global__ void k2b_bias(const float* __restrict__ b_hid) {
    const int e = threadIdx.x;
    const float4* b4 = reinterpret_cast<const float4*>(b_hid);
    const float4* r4 = reinterpret_cast<const float4*>(g_remb + e * RQ);
    float acc = 0.f;
    for (int r = 0; r < RQ / 4; r++) {
        float4 b = b4[r];
        float4 rr = r4[r];
        acc += b.x * rr.x + b.y * rr.y + b.z * rr.z + b.w * rr.w;
    }
    g_bias[e] = acc;
}

// ---------------------------------------------------------------------------
// K3: logits[t][e] = input[t][:] . W_comb[:][e] + bias[e], then top-2 +
// renormalized softmax weights, fused in the epilogue.
// Tiling: BM=64 tokens, BN=64 experts (all), BK=32; 256 threads, 4x4 microtile.
// grid = TQ/64 = 512 blocks.
// ---------------------------------------------------------------------------
__global__ __launch_bounds__(256) void k3_main(const float* __restrict__ input,
                                               float* __restrict__ out_idx,
                                               float* __restrict__ out_w,
                                               float* __restrict__ aux_ptr) {
    // union: [sA 64x36 | sB 32x64]  reused as  slog 64x65 in epilogue
    __shared__ float s[64 * 36 + 32 * 64];   // 4352 floats
    float* sA = s;               // [tok][36] (pad 36 keeps float4 stores aligned)
    float* sB = s + 64 * 36;     // [k][64]

    const int tid  = threadIdx.x;
    const int tok0 = blockIdx.x * 64;
    const int tm   = tid >> 4;   // 0..15 -> 4 tokens each
    const int tn   = tid & 15;   // 0..15 -> 4 experts each

    float acc[4][4];
#pragma unroll
    for (int i = 0; i < 4; i++)
#pragma unroll
        for (int j = 0; j < 4; j++) acc[i][j] = 0.f;

    const float4* A4 = reinterpret_cast<const float4*>(input) + (size_t)tok0 * (DQ / 4);
    const float4* W4 = reinterpret_cast<const float4*>(g_wcomb);

    for (int k0 = 0; k0 < DQ; k0 += 32) {
        // stage A tile: 64 tokens x 32 k (512 float4, 2 per thread), coalesced
#pragma unroll
        for (int u = 0; u < 2; u++) {
            int idx = tid + u * 256;
            int tok = idx >> 3;
            int kq  = idx & 7;
            float4 v = A4[tok * (DQ / 4) + (k0 >> 2) + kq];
            *reinterpret_cast<float4*>(&sA[tok * 36 + kq * 4]) = v;
        }
        // stage B tile: rows k0..k0+31 of W_comb are contiguous (2048 floats)
#pragma unroll
        for (int u = 0; u < 2; u++) {
            int idx = tid + u * 256;
            *reinterpret_cast<float4*>(&sB[idx * 4]) = W4[k0 * 16 + idx];
        }
        __syncthreads();

#pragma unroll 8
        for (int k = 0; k < 32; k++) {
            float a0 = sA[(tm * 4 + 0) * 36 + k];
            float a1 = sA[(tm * 4 + 1) * 36 + k];
            float a2 = sA[(tm * 4 + 2) * 36 + k];
            float a3 = sA[(tm * 4 + 3) * 36 + k];
            float4 b = *reinterpret_cast<const float4*>(&sB[k * 64 + tn * 4]);
            acc[0][0] += a0 * b.x; acc[0][1] += a0 * b.y; acc[0][2] += a0 * b.z; acc[0][3] += a0 * b.w;
            acc[1][0] += a1 * b.x; acc[1][1] += a1 * b.y; acc[1][2] += a1 * b.z; acc[1][3] += a1 * b.w;
            acc[2][0] += a2 * b.x; acc[2][1] += a2 * b.y; acc[2][2] += a2 * b.z; acc[2][3] += a2 * b.w;
            acc[3][0] += a3 * b.x; acc[3][1] += a3 * b.y; acc[3][2] += a3 * b.z; acc[3][3] += a3 * b.w;
        }
        __syncthreads();
    }

    // ---- epilogue: logits -> smem (padded 65 to kill bank conflicts) ----
    float* slog = s;   // [64][65], fits in the union (4160 <= 4352)
    float bias[4];
#pragma unroll
    for (int j = 0; j < 4; j++) bias[j] = g_bias[tn * 4 + j];
#pragma unroll
    for (int i = 0; i < 4; i++)
#pragma unroll
        for (int j = 0; j < 4; j++)
            slog[(tm * 4 + i) * 65 + tn * 4 + j] = acc[i][j] + bias[j];
    __syncthreads();

    // top-2 per token (strict > matches jax top_k lower-index tie-break),
    // weights = renormalized top-2 softmax = softmax over the 2 top logits.
    if (tid < 64) {
        const int t = tid;
        float best = -INFINITY, second = -INFINITY;
        int bi = 0, si = 0;
#pragma unroll 8
        for (int e = 0; e < EQ; e++) {
            float v = slog[t * 65 + e];
            if (v > best)        { second = best; si = bi; best = v; bi = e; }
            else if (v > second) { second = v; si = e; }
        }
        float es  = expf(second - best);   // in (0,1]
        float inv = 1.f / (1.f + es);
        int gt = tok0 + t;
        out_idx[gt * 2 + 0] = (float)bi;
        out_idx[gt * 2 + 1] = (float)si;
        out_w[gt * 2 + 0]   = inv;
        out_w[gt * 2 + 1]   = es * inv;
    }

    // aux loss is exactly (2/64)*0.5*64^2 = 64.0 for distinct top-2 indices
    if (blockIdx.x == 0 && tid == 0 && aux_ptr != nullptr) *aux_ptr = 64.0f;
}

// ---------------------------------------------------------------------------
// Inputs (metadata order): input, W_hid, b_hid, W_exp, b_exp, embeddings
// Output (flattened tuple, float32): selected_experts[B,S,2], routing_weights[B,S,2], aux_loss
// ---------------------------------------------------------------------------
extern "C" void kernel_launch(void* const* d_in, const int* in_sizes, int n_in,
                              void* d_out, int out_size) {
    const float* input = (const float*)d_in[0];
    const float* W_hid = (const float*)d_in[1];
    const float* b_hid = (const float*)d_in[2];
    const float* W_exp = (const float*)d_in[3];
    const float* b_exp = (const float*)d_in[4];
    const float* emb   = (const float*)d_in[5];

    float* out     = (float*)d_out;
    float* out_idx = out;                 // [TQ*2]
    float* out_w   = out + 2 * TQ;        // [TQ*2]
    float* aux     = (out_size > 4 * TQ) ? (out + (out_size - 1)) : nullptr;

    k1_remb<<<dim3(RQ / 256, EQ), 256>>>(W_exp, b_exp, emb);
    k2_wcomb<<<dim3(DQ / 256, EQ / 8), 256>>>(W_hid);
    k2b_bias<<<1, EQ>>>(b_hid);
    k3_main<<<TQ / 64, 256>>>(input, out_idx, out_w, aux);
}

// round 3
// speedup vs baseline: 1.8219x; 1.8219x over previous
#include <cuda_runtime.h>
#include <math.h>

// Problem dims
#define BQ    4
#define SQ    8192
#define DQ    2048      // input feature dim
#define RQ    1024      // RKHS
#define MQ    128       // EMB
#define EQ    64        // experts
#define TQ    32768     // tokens = B*S

#define PADA  68        // padded row stride (floats) for transposed A tile (16B aligned)

// Scratch (no allocation allowed -> __device__ globals)
__device__ float g_remb[EQ * RQ];        // rkhs_emb[e][r]
__device__ float g_rembT[RQ * EQ];       // rkhs_emb transposed [r][e]
__device__ float g_wcomb[DQ * EQ];       // W_comb[d][e]
__device__ float g_partial[8][DQ * EQ];  // split-K partials for W_comb (4MB)
__device__ float g_bias[EQ];             // bias_comb[e]

// ---------------------------------------------------------------------------
// K1: rkhs_emb[e][r] = sum_m emb[e][m] * W_exp[r][m] + b_exp[r]
// grid (EQ), 256 threads (8 warps). Warp w handles r in [w*128, w*128+128).
// Lanes split EMB: lane reads float4 at m=4*lane -> 512B coalesced per row.
// ---------------------------------------------------------------------------
__global__ void k1_remb(const float* __restrict__ W_exp,
                        const float* __restrict__ b_exp,
                        const float* __restrict__ emb) {
    __shared__ float4 s_emb[MQ / 4];
    const int e    = blockIdx.x;
    const int tid  = threadIdx.x;
    const int w    = tid >> 5;
    const int lane = tid & 31;
    if (tid < MQ / 4) s_emb[tid] = reinterpret_cast<const float4*>(emb)[e * (MQ / 4) + tid];
    __syncthreads();
    const float4 ev = s_emb[lane];
#pragma unroll 4
    for (int i = 0; i < 128; i++) {
        const int r = w * 128 + i;
        float4 wv = reinterpret_cast<const float4*>(W_exp)[r * (MQ / 4) + lane];
        float p = wv.x * ev.x + wv.y * ev.y + wv.z * ev.z + wv.w * ev.w;
        p += __shfl_xor_sync(0xffffffffu, p, 16);
        p += __shfl_xor_sync(0xffffffffu, p, 8);
        p += __shfl_xor_sync(0xffffffffu, p, 4);
        p += __shfl_xor_sync(0xffffffffu, p, 2);
        p += __shfl_xor_sync(0xffffffffu, p, 1);
        if (lane == 0) {
            float v = p + b_exp[r];
            g_remb[e * RQ + r]  = v;
            g_rembT[r * EQ + e] = v;
        }
    }
}

// ---------------------------------------------------------------------------
// K2: split-K GEMM: partial[p][d][e] = sum_{r in chunk p} W_hid[r][d] * rembT[r][e]
// Both operands are r-major: no transposes. grid (DQ/64, 8), 256 threads.
// Tile: 64 d x 64 e x 128 r (BK=16), 4x4 microtile.
// ---------------------------------------------------------------------------
__global__ __launch_bounds__(256) void k2_part(const float* __restrict__ W_hid) {
    __shared__ float sW[16 * PADA];   // [r][d], padded
    __shared__ float sR[16 * 64];     // [r][e]
    const int tid = threadIdx.x;
    const int d0  = blockIdx.x * 64;
    const int r0  = blockIdx.y * 128;
    const int tm  = tid >> 4;
    const int tn  = tid & 15;
    const int rr  = tid >> 4;   // staging row (0..15)
    const int dq  = tid & 15;   // staging float4 col

    float acc[4][4];
#pragma unroll
    for (int i = 0; i < 4; i++)
#pragma unroll
        for (int j = 0; j < 4; j++) acc[i][j] = 0.f;

    const float4* RT4 = reinterpret_cast<const float4*>(g_rembT);

    for (int rk = 0; rk < 128; rk += 16) {
        *reinterpret_cast<float4*>(&sW[rr * PADA + dq * 4]) =
            *reinterpret_cast<const float4*>(&W_hid[(size_t)(r0 + rk + rr) * DQ + d0 + dq * 4]);
        *reinterpret_cast<float4*>(&sR[tid * 4]) = RT4[(size_t)(r0 + rk) * (EQ / 4) + tid];
        __syncthreads();
#pragma unroll
        for (int k = 0; k < 16; k++) {
            float4 a = *reinterpret_cast<const float4*>(&sW[k * PADA + tm * 4]);
            float4 b = *reinterpret_cast<const float4*>(&sR[k * 64 + tn * 4]);
            acc[0][0] += a.x * b.x; acc[0][1] += a.x * b.y; acc[0][2] += a.x * b.z; acc[0][3] += a.x * b.w;
            acc[1][0] += a.y * b.x; acc[1][1] += a.y * b.y; acc[1][2] += a.y * b.z; acc[1][3] += a.y * b.w;
            acc[2][0] += a.z * b.x; acc[2][1] += a.z * b.y; acc[2][2] += a.z * b.z; acc[2][3] += a.z * b.w;
            acc[3][0] += a.w * b.x; acc[3][1] += a.w * b.y; acc[3][2] += a.w * b.z; acc[3][3] += a.w * b.w;
        }
        __syncthreads();
    }
    float* dst = &g_partial[blockIdx.y][0];
#pragma unroll
    for (int i = 0; i < 4; i++)
#pragma unroll
        for (int j = 0; j < 4; j++)
            dst[(size_t)(d0 + tm * 4 + i) * EQ + tn * 4 + j] = acc[i][j];
}

// K2r: reduce split-K partials into g_wcomb. Fixed order -> deterministic.
__global__ void k2_reduce() {
    const int i = blockIdx.x * 256 + threadIdx.x;   // float4 index, 32768 total
    float4 s = make_float4(0.f, 0.f, 0.f, 0.f);
#pragma unroll
    for (int p = 0; p < 8; p++) {
        float4 v = reinterpret_cast<const float4*>(&g_partial[p][0])[i];
        s.x += v.x; s.y += v.y; s.z += v.z; s.w += v.w;
    }
    reinterpret_cast<float4*>(g_wcomb)[i] = s;
}

// K2b: bias_comb[e] = sum_r b_hid[r] * rkhs_emb[e][r]   (1 block, 64 threads)
__global__ void k2b_bias(const float* __restrict__ b_hid) {
    const int e = threadIdx.x;
    const float4* b4 = reinterpret_cast<const float4*>(b_hid);
    const float4* r4 = reinterpret_cast<const float4*>(g_remb + e * RQ);
    float acc = 0.f;
    for (int r = 0; r < RQ / 4; r++) {
        float4 b = b4[r];
        float4 rr = r4[r];
        acc += b.x * rr.x + b.y * rr.y + b.z * rr.z + b.w * rr.w;
    }
    g_bias[e] = acc;
}

// ---------------------------------------------------------------------------
// K3: logits[t][e] = input[t][:] . W_comb[:][e] + bias[e], fused top-2.
// BM=64 tokens, BN=64 experts, BK=32. 256 threads, 4x4 microtile.
// A tile stored TRANSPOSED ([k][tok], pad PADA) so the A fragment is 1 LDS.128.
// Register-prefetch double buffering: one __syncthreads per iteration.
// ---------------------------------------------------------------------------
__global__ __launch_bounds__(256) void k3_main(const float* __restrict__ input,
                                               float* __restrict__ out_idx,
                                               float* __restrict__ out_w,
                                               float* __restrict__ aux_ptr) {
    // buffer: [sAT 32 x PADA | sB 32 x 64] = 2176 + 2048 = 4224 floats, x2
    __shared__ float s[2 * (32 * PADA + 32 * 64)];

    const int tid  = threadIdx.x;
    const int tok0 = blockIdx.x * 64;
    const int tm   = tid >> 4;
    const int tn   = tid & 15;

    // staging coords: A covers 64 tok x 32 k = 512 float4 (2/thread)
    const int st  = tid >> 3;      // token for u=0 (0..31); u=1 -> +32
    const int skq = tid & 7;       // k-float4 within tile

    float acc[4][4];
#pragma unroll
    for (int i = 0; i < 4; i++)
#pragma unroll
        for (int j = 0; j < 4; j++) acc[i][j] = 0.f;

    const float4* A4 = reinterpret_cast<const float4*>(input) + (size_t)tok0 * (DQ / 4);
    const float4* W4 = reinterpret_cast<const float4*>(g_wcomb);

    float4 ra0, ra1, rb0, rb1;
    // prefetch tile 0
    ra0 = A4[(size_t)st * (DQ / 4) + skq];
    ra1 = A4[(size_t)(st + 32) * (DQ / 4) + skq];
    rb0 = W4[tid];
    rb1 = W4[tid + 256];

    float* sAT0 = s;
    float* sB0  = s + 32 * PADA;
    float* sAT1 = s + 4224;
    float* sB1  = sAT1 + 32 * PADA;

    // store tile 0 -> buffer 0
    sAT0[(skq * 4 + 0) * PADA + st]      = ra0.x;
    sAT0[(skq * 4 + 1) * PADA + st]      = ra0.y;
    sAT0[(skq * 4 + 2) * PADA + st]      = ra0.z;
    sAT0[(skq * 4 + 3) * PADA + st]      = ra0.w;
    sAT0[(skq * 4 + 0) * PADA + st + 32] = ra1.x;
    sAT0[(skq * 4 + 1) * PADA + st + 32] = ra1.y;
    sAT0[(skq * 4 + 2) * PADA + st + 32] = ra1.z;
    sAT0[(skq * 4 + 3) * PADA + st + 32] = ra1.w;
    *reinterpret_cast<float4*>(&sB0[tid * 4])         = rb0;
    *reinterpret_cast<float4*>(&sB0[(tid + 256) * 4]) = rb1;
    __syncthreads();

    float* sA_c = sAT0; float* sB_c = sB0;
    float* sA_n = sAT1; float* sB_n = sB1;

    for (int it = 0; it < DQ / 32; it++) {
        const int k0n = (it + 1) * 32;
        if (it < DQ / 32 - 1) {
            ra0 = A4[(size_t)st * (DQ / 4) + (k0n >> 2) + skq];
            ra1 = A4[(size_t)(st + 32) * (DQ / 4) + (k0n >> 2) + skq];
            rb0 = W4[k0n * 16 + tid];
            rb1 = W4[k0n * 16 + tid + 256];
        }

#pragma unroll
        for (int k = 0; k < 32; k++) {
            float4 a = *reinterpret_cast<const float4*>(&sA_c[k * PADA + tm * 4]);
            float4 b = *reinterpret_cast<const float4*>(&sB_c[k * 64 + tn * 4]);
            acc[0][0] += a.x * b.x; acc[0][1] += a.x * b.y; acc[0][2] += a.x * b.z; acc[0][3] += a.x * b.w;
            acc[1][0] += a.y * b.x; acc[1][1] += a.y * b.y; acc[1][2] += a.y * b.z; acc[1][3] += a.y * b.w;
            acc[2][0] += a.z * b.x; acc[2][1] += a.z * b.y; acc[2][2] += a.z * b.z; acc[2][3] += a.z * b.w;
            acc[3][0] += a.w * b.x; acc[3][1] += a.w * b.y; acc[3][2] += a.w * b.z; acc[3][3] += a.w * b.w;
        }

        if (it < DQ / 32 - 1) {
            sA_n[(skq * 4 + 0) * PADA + st]      = ra0.x;
            sA_n[(skq * 4 + 1) * PADA + st]      = ra0.y;
            sA_n[(skq * 4 + 2) * PADA + st]      = ra0.z;
            sA_n[(skq * 4 + 3) * PADA + st]      = ra0.w;
            sA_n[(skq * 4 + 0) * PADA + st + 32] = ra1.x;
            sA_n[(skq * 4 + 1) * PADA + st + 32] = ra1.y;
            sA_n[(skq * 4 + 2) * PADA + st + 32] = ra1.z;
            sA_n[(skq * 4 + 3) * PADA + st + 32] = ra1.w;
            *reinterpret_cast<float4*>(&sB_n[tid * 4])         = rb0;
            *reinterpret_cast<float4*>(&sB_n[(tid + 256) * 4]) = rb1;
            // swap buffers
            float* t;
            t = sA_c; sA_c = sA_n; sA_n = t;
            t = sB_c; sB_c = sB_n; sB_n = t;
        }
        __syncthreads();
    }

    // ---- epilogue: logits -> smem (padded 65 to kill bank conflicts) ----
    float* slog = s;   // [64][65] = 4160 floats, fits
    float bias[4];
#pragma unroll
    for (int j = 0; j < 4; j++) bias[j] = g_bias[tn * 4 + j];
#pragma unroll
    for (int i = 0; i < 4; i++)
#pragma unroll
        for (int j = 0; j < 4; j++)
            slog[(tm * 4 + i) * 65 + tn * 4 + j] = acc[i][j] + bias[j];
    __syncthreads();

    // top-2 per token (strict > matches jax top_k lower-index tie-break),
    // weights = softmax over the two top logits.
    if (tid < 64) {
        const int t = tid;
        float best = -INFINITY, second = -INFINITY;
        int bi = 0, si = 0;
#pragma unroll 8
        for (int e = 0; e < EQ; e++) {
            float v = slog[t * 65 + e];
            if (v > best)        { second = best; si = bi; best = v; bi = e; }
            else if (v > second) { second = v; si = e; }
        }
        float es  = expf(second - best);   // in (0,1]
        float inv = 1.f / (1.f + es);
        int gt = tok0 + t;
        out_idx[gt * 2 + 0] = (float)bi;
        out_idx[gt * 2 + 1] = (float)si;
        out_w[gt * 2 + 0]   = inv;
        out_w[gt * 2 + 1]   = es * inv;
    }

    // aux loss is exactly (2/64)*0.5*64^2 = 64.0 for distinct top-2 indices
    if (blockIdx.x == 0 && tid == 0 && aux_ptr != nullptr) *aux_ptr = 64.0f;
}

// ---------------------------------------------------------------------------
// Inputs (metadata order): input, W_hid, b_hid, W_exp, b_exp, embeddings
// Output (float32): selected_experts[B,S,2], routing_weights[B,S,2], aux_loss
// ---------------------------------------------------------------------------
extern "C" void kernel_launch(void* const* d_in, const int* in_sizes, int n_in,
                              void* d_out, int out_size) {
    const float* input = (const float*)d_in[0];
    const float* W_hid = (const float*)d_in[1];
    const float* b_hid = (const float*)d_in[2];
    const float* W_exp = (const float*)d_in[3];
    const float* b_exp = (const float*)d_in[4];
    const float* emb   = (const float*)d_in[5];

    float* out     = (float*)d_out;
    float* out_idx = out;                 // [TQ*2]
    float* out_w   = out + 2 * TQ;        // [TQ*2]
    float* aux     = (out_size > 4 * TQ) ? (out + (out_size - 1)) : nullptr;

    k1_remb<<<EQ, 256>>>(W_exp, b_exp, emb);
    k2_part<<<dim3(DQ / 64, 8), 256>>>(W_hid);
    k2_reduce<<<(DQ * EQ / 4) / 256, 256>>>();
    k2b_bias<<<1, EQ>>>(b_hid);
    k3_main<<<TQ / 64, 256>>>(input, out_idx, out_w, aux);
}

// round 6
// speedup vs baseline: 2.6208x; 1.4385x over previous
#include <cuda_runtime.h>
#include <math.h>
#include <stdint.h>

// Problem dims
#define DQ    2048
#define RQ    1024
#define MQ    128
#define EQ    64
#define TQ    32768
#define PADA  68

// k3 tiling
#define KC        16
#define PAD       20                       // floats per staged row (16 + 4) -> all-32-bank pattern
#define ST_FLOATS (128*PAD*2 + 64*PAD*2)   // Ah,Al (128 rows) + Bh,Bl (64 rows) = 7680 floats
#define OFF_STAGE 64                       // floats; bias lives in [0,64)
#define K3_SMEM_BYTES ((OFF_STAGE + 2*ST_FLOATS) * 4)   // 61696

// ---------------- scratch ----------------
__device__ float g_remb[EQ * RQ];
__device__ float g_rembT[RQ * EQ];
__device__ float g_partialT[8][EQ * DQ];   // [e][d]
__device__ float g_BhiT[EQ * DQ];          // tf32-hi of W_combT [e][d]
__device__ float g_BloT[EQ * DQ];          // tf32-lo
__device__ float g_bias[EQ];

__device__ __forceinline__ float tf_hi(float x) {
    return __uint_as_float(__float_as_uint(x) & 0xFFFFE000u);
}
__device__ __forceinline__ uint32_t fbits(float x) { return __float_as_uint(x); }

// m16n8k8 tf32 mma, D += A*B (row.col)
__device__ __forceinline__ void mma8(float* d, const uint32_t* a, uint32_t b0, uint32_t b1) {
    asm volatile(
        "mma.sync.aligned.m16n8k8.row.col.f32.tf32.tf32.f32 "
        "{%0,%1,%2,%3}, {%4,%5,%6,%7}, {%8,%9}, {%0,%1,%2,%3};"
        : "+f"(d[0]), "+f"(d[1]), "+f"(d[2]), "+f"(d[3])
        : "r"(a[0]), "r"(a[1]), "r"(a[2]), "r"(a[3]), "r"(b0), "r"(b1));
}

// ---------------------------------------------------------------------------
// K1: rkhs_emb[e][r] = sum_m emb[e][m] * W_exp[r][m] + b_exp[r]
// ---------------------------------------------------------------------------
__global__ void k1_remb(const float* __restrict__ W_exp,
                        const float* __restrict__ b_exp,
                        const float* __restrict__ emb) {
    __shared__ float4 s_emb[MQ / 4];
    const int e    = blockIdx.x;
    const int tid  = threadIdx.x;
    const int w    = tid >> 5;
    const int lane = tid & 31;
    if (tid < MQ / 4) s_emb[tid] = reinterpret_cast<const float4*>(emb)[e * (MQ / 4) + tid];
    __syncthreads();
    const float4 ev = s_emb[lane];
#pragma unroll 4
    for (int i = 0; i < 128; i++) {
        const int r = w * 128 + i;
        float4 wv = reinterpret_cast<const float4*>(W_exp)[r * (MQ / 4) + lane];
        float p = wv.x * ev.x + wv.y * ev.y + wv.z * ev.z + wv.w * ev.w;
        p += __shfl_xor_sync(0xffffffffu, p, 16);
        p += __shfl_xor_sync(0xffffffffu, p, 8);
        p += __shfl_xor_sync(0xffffffffu, p, 4);
        p += __shfl_xor_sync(0xffffffffu, p, 2);
        p += __shfl_xor_sync(0xffffffffu, p, 1);
        if (lane == 0) {
            float v = p + b_exp[r];
            g_remb[e * RQ + r]  = v;
            g_rembT[r * EQ + e] = v;
        }
    }
}

// ---------------------------------------------------------------------------
// K2: split-K GEMM -> partials of W_combT[e][d]
// ---------------------------------------------------------------------------
__global__ __launch_bounds__(256) void k2_part(const float* __restrict__ W_hid) {
    __shared__ float sW[16 * PADA];
    __shared__ float sR[16 * 64];
    const int tid = threadIdx.x;
    const int d0  = blockIdx.x * 64;
    const int r0  = blockIdx.y * 128;
    const int tm  = tid >> 4;
    const int tn  = tid & 15;
    const int rr  = tid >> 4;
    const int dq  = tid & 15;

    float acc[4][4];
#pragma unroll
    for (int i = 0; i < 4; i++)
#pragma unroll
        for (int j = 0; j < 4; j++) acc[i][j] = 0.f;

    const float4* RT4 = reinterpret_cast<const float4*>(g_rembT);

    for (int rk = 0; rk < 128; rk += 16) {
        *reinterpret_cast<float4*>(&sW[rr * PADA + dq * 4]) =
            *reinterpret_cast<const float4*>(&W_hid[(size_t)(r0 + rk + rr) * DQ + d0 + dq * 4]);
        *reinterpret_cast<float4*>(&sR[tid * 4]) = RT4[(size_t)(r0 + rk) * (EQ / 4) + tid];
        __syncthreads();
#pragma unroll
        for (int k = 0; k < 16; k++) {
            float4 a = *reinterpret_cast<const float4*>(&sW[k * PADA + tm * 4]);
            float4 b = *reinterpret_cast<const float4*>(&sR[k * 64 + tn * 4]);
            acc[0][0] += a.x * b.x; acc[0][1] += a.x * b.y; acc[0][2] += a.x * b.z; acc[0][3] += a.x * b.w;
            acc[1][0] += a.y * b.x; acc[1][1] += a.y * b.y; acc[1][2] += a.y * b.z; acc[1][3] += a.y * b.w;
            acc[2][0] += a.z * b.x; acc[2][1] += a.z * b.y; acc[2][2] += a.z * b.z; acc[2][3] += a.z * b.w;
            acc[3][0] += a.w * b.x; acc[3][1] += a.w * b.y; acc[3][2] += a.w * b.z; acc[3][3] += a.w * b.w;
        }
        __syncthreads();
    }
    float* dst = &g_partialT[blockIdx.y][0];
#pragma unroll
    for (int i = 0; i < 4; i++)
#pragma unroll
        for (int j = 0; j < 4; j++)
            dst[(size_t)(tn * 4 + j) * DQ + d0 + tm * 4 + i] = acc[i][j];
}

// K2r: reduce partials, split into tf32 hi/lo (exact truncation split)
__global__ void k2_reduce() {
    const int i = blockIdx.x * 256 + threadIdx.x;
    float4 s = make_float4(0.f, 0.f, 0.f, 0.f);
#pragma unroll
    for (int p = 0; p < 8; p++) {
        float4 v = reinterpret_cast<const float4*>(&g_partialT[p][0])[i];
        s.x += v.x; s.y += v.y; s.z += v.z; s.w += v.w;
    }
    float4 hi, lo;
    hi.x = tf_hi(s.x); lo.x = tf_hi(s.x - hi.x);
    hi.y = tf_hi(s.y); lo.y = tf_hi(s.y - hi.y);
    hi.z = tf_hi(s.z); lo.z = tf_hi(s.z - hi.z);
    hi.w = tf_hi(s.w); lo.w = tf_hi(s.w - hi.w);
    reinterpret_cast<float4*>(g_BhiT)[i] = hi;
    reinterpret_cast<float4*>(g_BloT)[i] = lo;
}

// K2b: bias_comb[e] = dot(b_hid, rkhs_emb[e]) — one block per expert
__global__ void k2b_bias(const float* __restrict__ b_hid) {
    __shared__ float red[4];
    const int e   = blockIdx.x;
    const int tid = threadIdx.x;
    const float4* b4 = reinterpret_cast<const float4*>(b_hid);
    const float4* r4 = reinterpret_cast<const float4*>(g_remb + e * RQ);
    float acc = 0.f;
#pragma unroll
    for (int i = 0; i < 2; i++) {
        int idx = tid + i * 128;
        float4 b = b4[idx], r = r4[idx];
        acc += b.x * r.x + b.y * r.y + b.z * r.z + b.w * r.w;
    }
#pragma unroll
    for (int o = 16; o; o >>= 1) acc += __shfl_xor_sync(0xffffffffu, acc, o);
    if ((tid & 31) == 0) red[tid >> 5] = acc;
    __syncthreads();
    if (tid == 0) g_bias[e] = (red[0] + red[1]) + (red[2] + red[3]);
}

// ---------------------------------------------------------------------------
// K3: 3xTF32 mma.sync GEMM [128 tok x 64 exp x 2048] + fused top-2.
// 128 threads (4 warps), warp tile 32x64 (2 m-blocks x 8 n-blocks).
// ---------------------------------------------------------------------------
__global__ __launch_bounds__(128, 2) void k3_mma(const float* __restrict__ input,
                                                 float* __restrict__ out_idx,
                                                 float* __restrict__ out_w,
                                                 float* __restrict__ aux_ptr) {
    extern __shared__ float sm[];
    float* sbias = sm;                       // [0,64)
    const int tid  = threadIdx.x;
    const int w    = tid >> 5;
    const int lane = tid & 31;
    const int g    = lane >> 2;
    const int c    = lane & 3;
    const int tok0 = blockIdx.x * 128;

    if (tid < EQ) sbias[tid] = g_bias[tid];

    float acc[2][8][4];
#pragma unroll
    for (int i = 0; i < 2; i++)
#pragma unroll
        for (int j = 0; j < 8; j++)
#pragma unroll
            for (int q = 0; q < 4; q++) acc[i][j][q] = 0.f;

    const float4* A4  = reinterpret_cast<const float4*>(input);
    const float4* Bh4 = reinterpret_cast<const float4*>(g_BhiT);
    const float4* Bl4 = reinterpret_cast<const float4*>(g_BloT);

    // staging coords: A thread -> row (tid>>2)+32u, f4-col tid&3 ; B idx = tid+128u
    const int arow = tid >> 2, aj = tid & 3;

    float4 pa[4], pbh[2], pbl[2];
#pragma unroll
    for (int u = 0; u < 4; u++)
        pa[u] = A4[(size_t)(tok0 + arow + 32 * u) * (DQ / 4) + aj];
#pragma unroll
    for (int u = 0; u < 2; u++) {
        int idx = tid + 128 * u;
        pbh[u] = Bh4[(size_t)(idx >> 2) * (DQ / 4) + (idx & 3)];
        pbl[u] = Bl4[(size_t)(idx >> 2) * (DQ / 4) + (idx & 3)];
    }

    // store chunk 0 into stage 0
#pragma unroll
    for (int u = 0; u < 4; u++) {
        float4 v = pa[u];
        float4 hi = make_float4(tf_hi(v.x), tf_hi(v.y), tf_hi(v.z), tf_hi(v.w));
        float4 lo = make_float4(tf_hi(v.x - hi.x), tf_hi(v.y - hi.y),
                                tf_hi(v.z - hi.z), tf_hi(v.w - hi.w));
        int row = arow + 32 * u;
        *reinterpret_cast<float4*>(&sm[OFF_STAGE + row * PAD + aj * 4])            = hi;
        *reinterpret_cast<float4*>(&sm[OFF_STAGE + 128 * PAD + row * PAD + aj * 4]) = lo;
    }
#pragma unroll
    for (int u = 0; u < 2; u++) {
        int idx = tid + 128 * u;
        *reinterpret_cast<float4*>(&sm[OFF_STAGE + 256 * PAD + (idx >> 2) * PAD + (idx & 3) * 4]) = pbh[u];
        *reinterpret_cast<float4*>(&sm[OFF_STAGE + 320 * PAD + (idx >> 2) * PAD + (idx & 3) * 4]) = pbl[u];
    }
    __syncthreads();

    for (int ch = 0; ch < DQ / KC; ch++) {
        const int cur = ch & 1;
        const float* Ah = sm + OFF_STAGE + cur * ST_FLOATS;
        const float* Al = Ah + 128 * PAD;
        const float* Bh = Ah + 256 * PAD;
        const float* Bl = Ah + 320 * PAD;

        if (ch < DQ / KC - 1) {
            const int k4 = (ch + 1) * (KC / 4);
#pragma unroll
            for (int u = 0; u < 4; u++)
                pa[u] = A4[(size_t)(tok0 + arow + 32 * u) * (DQ / 4) + k4 + aj];
#pragma unroll
            for (int u = 0; u < 2; u++) {
                int idx = tid + 128 * u;
                pbh[u] = Bh4[(size_t)(idx >> 2) * (DQ / 4) + k4 + (idx & 3)];
                pbl[u] = Bl4[(size_t)(idx >> 2) * (DQ / 4) + k4 + (idx & 3)];
            }
        }

#pragma unroll
        for (int ko = 0; ko < KC; ko += 8) {
            uint32_t ahf[2][4], alf[2][4];
#pragma unroll
            for (int i = 0; i < 2; i++) {
                const int rb = w * 32 + i * 16 + g;
                ahf[i][0] = fbits(Ah[rb * PAD + ko + c]);
                ahf[i][1] = fbits(Ah[(rb + 8) * PAD + ko + c]);
                ahf[i][2] = fbits(Ah[rb * PAD + ko + c + 4]);
                ahf[i][3] = fbits(Ah[(rb + 8) * PAD + ko + c + 4]);
                alf[i][0] = fbits(Al[rb * PAD + ko + c]);
                alf[i][1] = fbits(Al[(rb + 8) * PAD + ko + c]);
                alf[i][2] = fbits(Al[rb * PAD + ko + c + 4]);
                alf[i][3] = fbits(Al[(rb + 8) * PAD + ko + c + 4]);
            }
            // pass 1: hi*hi   (term-major -> long RAW distance per accumulator)
#pragma unroll
            for (int j = 0; j < 8; j++) {
                const int e = j * 8 + g;
                uint32_t b0 = fbits(Bh[e * PAD + ko + c]);
                uint32_t b1 = fbits(Bh[e * PAD + ko + c + 4]);
                mma8(acc[0][j], ahf[0], b0, b1);
                mma8(acc[1][j], ahf[1], b0, b1);
            }
            // pass 2: hi*lo
#pragma unroll
            for (int j = 0; j < 8; j++) {
                const int e = j * 8 + g;
                uint32_t b0 = fbits(Bl[e * PAD + ko + c]);
                uint32_t b1 = fbits(Bl[e * PAD + ko + c + 4]);
                mma8(acc[0][j], ahf[0], b0, b1);
                mma8(acc[1][j], ahf[1], b0, b1);
            }
            // pass 3: lo*hi
#pragma unroll
            for (int j = 0; j < 8; j++) {
                const int e = j * 8 + g;
                uint32_t b0 = fbits(Bh[e * PAD + ko + c]);
                uint32_t b1 = fbits(Bh[e * PAD + ko + c + 4]);
                mma8(acc[0][j], alf[0], b0, b1);
                mma8(acc[1][j], alf[1], b0, b1);
            }
        }

        if (ch < DQ / KC - 1) {
            float* nA = sm + OFF_STAGE + (1 - cur) * ST_FLOATS;
#pragma unroll
            for (int u = 0; u < 4; u++) {
                float4 v = pa[u];
                float4 hi = make_float4(tf_hi(v.x), tf_hi(v.y), tf_hi(v.z), tf_hi(v.w));
                float4 lo = make_float4(tf_hi(v.x - hi.x), tf_hi(v.y - hi.y),
                                        tf_hi(v.z - hi.z), tf_hi(v.w - hi.w));
                int row = arow + 32 * u;
                *reinterpret_cast<float4*>(&nA[row * PAD + aj * 4])             = hi;
                *reinterpret_cast<float4*>(&nA[128 * PAD + row * PAD + aj * 4]) = lo;
            }
#pragma unroll
            for (int u = 0; u < 2; u++) {
                int idx = tid + 128 * u;
                *reinterpret_cast<float4*>(&nA[256 * PAD + (idx >> 2) * PAD + (idx & 3) * 4]) = pbh[u];
                *reinterpret_cast<float4*>(&nA[320 * PAD + (idx >> 2) * PAD + (idx & 3) * 4]) = pbl[u];
            }
        }
        __syncthreads();
    }

    // ---- epilogue: logits -> smem [128][65], then top-2 per token ----
    float* slog = sm + OFF_STAGE;
#pragma unroll
    for (int i = 0; i < 2; i++) {
        const int r0 = w * 32 + i * 16 + g;
#pragma unroll
        for (int j = 0; j < 8; j++) {
            const int col = j * 8 + 2 * c;
            slog[r0 * 65 + col]           = acc[i][j][0] + sbias[col];
            slog[r0 * 65 + col + 1]       = acc[i][j][1] + sbias[col + 1];
            slog[(r0 + 8) * 65 + col]     = acc[i][j][2] + sbias[col];
            slog[(r0 + 8) * 65 + col + 1] = acc[i][j][3] + sbias[col + 1];
        }
    }
    __syncthreads();

    {
        const int t = tid;          // 128 tokens, 128 threads
        float best = -INFINITY, second = -INFINITY;
        int bi = 0, si = 0;
#pragma unroll 8
        for (int e = 0; e < EQ; e++) {
            float v = slog[t * 65 + e];
            if (v > best)        { second = best; si = bi; best = v; bi = e; }
            else if (v > second) { second = v; si = e; }
        }
        float es  = expf(second - best);
        float inv = 1.f / (1.f + es);
        int gt = tok0 + t;
        out_idx[gt * 2 + 0] = (float)bi;
        out_idx[gt * 2 + 1] = (float)si;
        out_w[gt * 2 + 0]   = inv;
        out_w[gt * 2 + 1]   = es * inv;
    }

    if (blockIdx.x == 0 && tid == 0 && aux_ptr != nullptr) *aux_ptr = 64.0f;
}

// ---------------------------------------------------------------------------
extern "C" void kernel_launch(void* const* d_in, const int* in_sizes, int n_in,
                              void* d_out, int out_size) {
    const float* input = (const float*)d_in[0];
    const float* W_hid = (const float*)d_in[1];
    const float* b_hid = (const float*)d_in[2];
    const float* W_exp = (const float*)d_in[3];
    const float* b_exp = (const float*)d_in[4];
    const float* emb   = (const float*)d_in[5];

    float* out     = (float*)d_out;
    float* out_idx = out;
    float* out_w   = out + 2 * TQ;
    float* aux     = (out_size > 4 * TQ) ? (out + (out_size - 1)) : nullptr;

    cudaFuncSetAttribute(k3_mma, cudaFuncAttributeMaxDynamicSharedMemorySize, K3_SMEM_BYTES);

    k1_remb<<<EQ, 256>>>(W_exp, b_exp, emb);
    k2_part<<<dim3(DQ / 64, 8), 256>>>(W_hid);
    k2_reduce<<<(EQ * DQ / 4) / 256, 256>>>();
    k2b_bias<<<EQ, 128>>>(b_hid);
    k3_mma<<<TQ / 128, 128, K3_SMEM_BYTES>>>(input, out_idx, out_w, aux);
}

// round 8
// speedup vs baseline: 3.6290x; 1.3847x over previous
#include <cuda_runtime.h>
#include <cuda_fp16.h>
#include <math.h>
#include <stdint.h>

// Problem dims
#define DQ    2048
#define RQ    1024
#define MQ    128
#define EQ    64
#define TQ    32768
#define PADA  68

// k3 tiling (fp16 x3, m16n8k16)
#define KC        16
#define SA2       24                      // halfs per staged A row (16+8) -> conflict-free frags
#define SB2       24
#define AH_HALFS  (128 * SA2)             // 3072
#define BH_HALFS  (64 * SB2)              // 1536
#define ST_HALFS  (2 * AH_HALFS + 2 * BH_HALFS)   // 9216 halfs = 18432 B
#define OFF_AH    0
#define OFF_AL    AH_HALFS
#define OFF_BH    (2 * AH_HALFS)
#define OFF_BL    (2 * AH_HALFS + BH_HALFS)
#define OFF_STAGE_H 128                   // halfs; bias floats occupy [0,64) floats = 128 halfs
#define K3_SMEM_BYTES ((OFF_STAGE_H + 2 * ST_HALFS) * 2)   // 37120 B

// ---------------- scratch ----------------
__device__ float  g_remb[EQ * RQ];
__device__ float  g_rembT[RQ * EQ];
__device__ float  g_partialT[8][EQ * DQ];   // [e][d] fp32
__device__ __half g_BhT[EQ * DQ];           // fp16-hi of W_combT [e][d]
__device__ __half g_BlT[EQ * DQ];           // fp16-lo
__device__ float  g_bias[EQ];

__device__ __forceinline__ float mask11(float x) {   // keep 11 significand bits (fp16-exact)
    return __uint_as_float(__float_as_uint(x) & 0xFFFFE000u);
}

// m16n8k16 fp16 mma, f32 accum, D += A*B (row.col)
__device__ __forceinline__ void mma16(float* d, const uint32_t* a, uint32_t b0, uint32_t b1) {
    asm volatile(
        "mma.sync.aligned.m16n8k16.row.col.f32.f16.f16.f32 "
        "{%0,%1,%2,%3}, {%4,%5,%6,%7}, {%8,%9}, {%0,%1,%2,%3};"
        : "+f"(d[0]), "+f"(d[1]), "+f"(d[2]), "+f"(d[3])
        : "r"(a[0]), "r"(a[1]), "r"(a[2]), "r"(a[3]), "r"(b0), "r"(b1));
}

__device__ __forceinline__ uint32_t pack_h2(float lo, float hi) {   // halfs {lo, hi} -> b32
    __half2 h = __floats2half2_rn(lo, hi);
    return *reinterpret_cast<uint32_t*>(&h);
}

// ---------------------------------------------------------------------------
// K1: rkhs_emb[e][r] = sum_m emb[e][m]*W_exp[r][m] + b_exp[r]; also fuses
// bias_comb[e] = sum_r b_hid[r]*rkhs_emb[e][r].
// ---------------------------------------------------------------------------
__global__ void k1_remb(const float* __restrict__ W_exp,
                        const float* __restrict__ b_exp,
                        const float* __restrict__ emb,
                        const float* __restrict__ b_hid) {
    __shared__ float4 s_emb[MQ / 4];
    __shared__ float  red[8];
    const int e    = blockIdx.x;
    const int tid  = threadIdx.x;
    const int w    = tid >> 5;
    const int lane = tid & 31;
    if (tid < MQ / 4) s_emb[tid] = reinterpret_cast<const float4*>(emb)[e * (MQ / 4) + tid];
    __syncthreads();
    const float4 ev = s_emb[lane];
    float bacc = 0.f;
#pragma unroll 4
    for (int i = 0; i < 128; i++) {
        const int r = w * 128 + i;
        float4 wv = reinterpret_cast<const float4*>(W_exp)[r * (MQ / 4) + lane];
        float p = wv.x * ev.x + wv.y * ev.y + wv.z * ev.z + wv.w * ev.w;
        p += __shfl_xor_sync(0xffffffffu, p, 16);
        p += __shfl_xor_sync(0xffffffffu, p, 8);
        p += __shfl_xor_sync(0xffffffffu, p, 4);
        p += __shfl_xor_sync(0xffffffffu, p, 2);
        p += __shfl_xor_sync(0xffffffffu, p, 1);
        if (lane == 0) {
            float v = p + b_exp[r];
            g_remb[e * RQ + r]  = v;
            g_rembT[r * EQ + e] = v;
            bacc += b_hid[r] * v;
        }
    }
    if (lane == 0) red[w] = bacc;
    __syncthreads();
    if (tid == 0) {
        float s = 0.f;
#pragma unroll
        for (int i = 0; i < 8; i++) s += red[i];
        g_bias[e] = s;
    }
}

// ---------------------------------------------------------------------------
// K2: split-K GEMM -> partials of W_combT[e][d]
// ---------------------------------------------------------------------------
__global__ __launch_bounds__(256) void k2_part(const float* __restrict__ W_hid) {
    __shared__ float sW[16 * PADA];
    __shared__ float sR[16 * 64];
    const int tid = threadIdx.x;
    const int d0  = blockIdx.x * 64;
    const int r0  = blockIdx.y * 128;
    const int tm  = tid >> 4;
    const int tn  = tid & 15;
    const int rr  = tid >> 4;
    const int dq  = tid & 15;

    float acc[4][4];
#pragma unroll
    for (int i = 0; i < 4; i++)
#pragma unroll
        for (int j = 0; j < 4; j++) acc[i][j] = 0.f;

    const float4* RT4 = reinterpret_cast<const float4*>(g_rembT);

    for (int rk = 0; rk < 128; rk += 16) {
        *reinterpret_cast<float4*>(&sW[rr * PADA + dq * 4]) =
            *reinterpret_cast<const float4*>(&W_hid[(size_t)(r0 + rk + rr) * DQ + d0 + dq * 4]);
        *reinterpret_cast<float4*>(&sR[tid * 4]) = RT4[(size_t)(r0 + rk) * (EQ / 4) + tid];
        __syncthreads();
#pragma unroll
        for (int k = 0; k < 16; k++) {
            float4 a = *reinterpret_cast<const float4*>(&sW[k * PADA + tm * 4]);
            float4 b = *reinterpret_cast<const float4*>(&sR[k * 64 + tn * 4]);
            acc[0][0] += a.x * b.x; acc[0][1] += a.x * b.y; acc[0][2] += a.x * b.z; acc[0][3] += a.x * b.w;
            acc[1][0] += a.y * b.x; acc[1][1] += a.y * b.y; acc[1][2] += a.y * b.z; acc[1][3] += a.y * b.w;
            acc[2][0] += a.z * b.x; acc[2][1] += a.z * b.y; acc[2][2] += a.z * b.z; acc[2][3] += a.z * b.w;
            acc[3][0] += a.w * b.x; acc[3][1] += a.w * b.y; acc[3][2] += a.w * b.z; acc[3][3] += a.w * b.w;
        }
        __syncthreads();
    }
    float* dst = &g_partialT[blockIdx.y][0];
#pragma unroll
    for (int i = 0; i < 4; i++)
#pragma unroll
        for (int j = 0; j < 4; j++)
            dst[(size_t)(tn * 4 + j) * DQ + d0 + tm * 4 + i] = acc[i][j];
}

// K2r: reduce partials, split into fp16 hi/lo (hi = fp16-exact 11-bit truncation)
__global__ void k2_reduce() {
    const int i = blockIdx.x * 256 + threadIdx.x;   // float4 index over EQ*DQ
    float4 s = make_float4(0.f, 0.f, 0.f, 0.f);
#pragma unroll
    for (int p = 0; p < 8; p++) {
        float4 v = reinterpret_cast<const float4*>(&g_partialT[p][0])[i];
        s.x += v.x; s.y += v.y; s.z += v.z; s.w += v.w;
    }
    float hx = mask11(s.x), hy = mask11(s.y), hz = mask11(s.z), hw = mask11(s.w);
    uint2 ho = make_uint2(pack_h2(hx, hy), pack_h2(hz, hw));
    uint2 lo = make_uint2(pack_h2(s.x - hx, s.y - hy), pack_h2(s.z - hz, s.w - hw));
    reinterpret_cast<uint2*>(g_BhT)[i] = ho;
    reinterpret_cast<uint2*>(g_BlT)[i] = lo;
}

// ---------------------------------------------------------------------------
// K3: fp16x3 mma.sync GEMM [128 tok x 64 exp x 2048] + fused top-2.
// 128 threads (4 warps), warp tile 32x64 (2 m-blocks x 8 n-blocks), KC=16.
// ---------------------------------------------------------------------------
__global__ __launch_bounds__(128, 2) void k3_mma(const float* __restrict__ input,
                                                 float* __restrict__ out_idx,
                                                 float* __restrict__ out_w,
                                                 float* __restrict__ aux_ptr) {
    extern __shared__ __half smh[];
    float* sbias = reinterpret_cast<float*>(smh);     // [0,64) floats
    __half* stg  = smh + OFF_STAGE_H;
    const int tid  = threadIdx.x;
    const int w    = tid >> 5;
    const int lane = tid & 31;
    const int g    = lane >> 2;
    const int c    = lane & 3;
    const int tok0 = blockIdx.x * 128;

    if (tid < EQ) sbias[tid] = g_bias[tid];

    float acc[2][8][4];
#pragma unroll
    for (int i = 0; i < 2; i++)
#pragma unroll
        for (int j = 0; j < 8; j++)
#pragma unroll
            for (int q = 0; q < 4; q++) acc[i][j][q] = 0.f;

    const float4* A4 = reinterpret_cast<const float4*>(input);

    // staging coords: A row = (tid>>2)+32u, float4-col aj = tid&3 (k = 4aj..4aj+3)
    //                 B: e = tid>>1, 8-half seg = tid&1
    const int arow = tid >> 2, aj = tid & 3;
    const int be = tid >> 1, bs = tid & 1;

    float4 pa[4];
    uint4  pbh, pbl;

    // prefetch + store chunk 0
#pragma unroll
    for (int u = 0; u < 4; u++)
        pa[u] = A4[(size_t)(tok0 + arow + 32 * u) * (DQ / 4) + aj];
    pbh = *reinterpret_cast<const uint4*>(g_BhT + (size_t)be * DQ + 8 * bs);
    pbl = *reinterpret_cast<const uint4*>(g_BlT + (size_t)be * DQ + 8 * bs);

#pragma unroll
    for (int u = 0; u < 4; u++) {
        float4 v = pa[u];
        float hx = mask11(v.x), hy = mask11(v.y), hz = mask11(v.z), hw = mask11(v.w);
        int row = arow + 32 * u;
        *reinterpret_cast<uint2*>(&stg[OFF_AH + row * SA2 + aj * 4]) =
            make_uint2(pack_h2(hx, hy), pack_h2(hz, hw));
        *reinterpret_cast<uint2*>(&stg[OFF_AL + row * SA2 + aj * 4]) =
            make_uint2(pack_h2(v.x - hx, v.y - hy), pack_h2(v.z - hz, v.w - hw));
    }
    *reinterpret_cast<uint4*>(&stg[OFF_BH + be * SB2 + 8 * bs]) = pbh;
    *reinterpret_cast<uint4*>(&stg[OFF_BL + be * SB2 + 8 * bs]) = pbl;
    __syncthreads();

    for (int ch = 0; ch < DQ / KC; ch++) {
        const int cur = ch & 1;
        const __half* Ah = stg + cur * ST_HALFS + OFF_AH;
        const __half* Al = stg + cur * ST_HALFS + OFF_AL;
        const __half* Bh = stg + cur * ST_HALFS + OFF_BH;
        const __half* Bl = stg + cur * ST_HALFS + OFF_BL;

        if (ch < DQ / KC - 1) {
            const int k4 = (ch + 1) * (KC / 4);
#pragma unroll
            for (int u = 0; u < 4; u++)
                pa[u] = A4[(size_t)(tok0 + arow + 32 * u) * (DQ / 4) + k4 + aj];
            pbh = *reinterpret_cast<const uint4*>(g_BhT + (size_t)be * DQ + k4 * 4 + 8 * bs);
            pbl = *reinterpret_cast<const uint4*>(g_BlT + (size_t)be * DQ + k4 * 4 + 8 * bs);
        }

        // A fragments (one k16 block covers the chunk)
        uint32_t ahf[2][4], alf[2][4];
#pragma unroll
        for (int i = 0; i < 2; i++) {
            const int rb = w * 32 + i * 16 + g;
            ahf[i][0] = *reinterpret_cast<const uint32_t*>(&Ah[rb * SA2 + 2 * c]);
            ahf[i][1] = *reinterpret_cast<const uint32_t*>(&Ah[(rb + 8) * SA2 + 2 * c]);
            ahf[i][2] = *reinterpret_cast<const uint32_t*>(&Ah[rb * SA2 + 2 * c + 8]);
            ahf[i][3] = *reinterpret_cast<const uint32_t*>(&Ah[(rb + 8) * SA2 + 2 * c + 8]);
            alf[i][0] = *reinterpret_cast<const uint32_t*>(&Al[rb * SA2 + 2 * c]);
            alf[i][1] = *reinterpret_cast<const uint32_t*>(&Al[(rb + 8) * SA2 + 2 * c]);
            alf[i][2] = *reinterpret_cast<const uint32_t*>(&Al[rb * SA2 + 2 * c + 8]);
            alf[i][3] = *reinterpret_cast<const uint32_t*>(&Al[(rb + 8) * SA2 + 2 * c + 8]);
        }

        // pass 1: hi*hi — cache Bh fragments for reuse in pass 3
        uint32_t bhf[8][2];
#pragma unroll
        for (int j = 0; j < 8; j++) {
            const int e = j * 8 + g;
            bhf[j][0] = *reinterpret_cast<const uint32_t*>(&Bh[e * SB2 + 2 * c]);
            bhf[j][1] = *reinterpret_cast<const uint32_t*>(&Bh[e * SB2 + 2 * c + 8]);
            mma16(acc[0][j], ahf[0], bhf[j][0], bhf[j][1]);
            mma16(acc[1][j], ahf[1], bhf[j][0], bhf[j][1]);
        }
        // pass 2: hi*lo
#pragma unroll
        for (int j = 0; j < 8; j++) {
            const int e = j * 8 + g;
            uint32_t b0 = *reinterpret_cast<const uint32_t*>(&Bl[e * SB2 + 2 * c]);
            uint32_t b1 = *reinterpret_cast<const uint32_t*>(&Bl[e * SB2 + 2 * c + 8]);
            mma16(acc[0][j], ahf[0], b0, b1);
            mma16(acc[1][j], ahf[1], b0, b1);
        }
        // pass 3: lo*hi (reuse cached Bh)
#pragma unroll
        for (int j = 0; j < 8; j++) {
            mma16(acc[0][j], alf[0], bhf[j][0], bhf[j][1]);
            mma16(acc[1][j], alf[1], bhf[j][0], bhf[j][1]);
        }

        if (ch < DQ / KC - 1) {
            __half* n = stg + (1 - cur) * ST_HALFS;
#pragma unroll
            for (int u = 0; u < 4; u++) {
                float4 v = pa[u];
                float hx = mask11(v.x), hy = mask11(v.y), hz = mask11(v.z), hw = mask11(v.w);
                int row = arow + 32 * u;
                *reinterpret_cast<uint2*>(&n[OFF_AH + row * SA2 + aj * 4]) =
                    make_uint2(pack_h2(hx, hy), pack_h2(hz, hw));
                *reinterpret_cast<uint2*>(&n[OFF_AL + row * SA2 + aj * 4]) =
                    make_uint2(pack_h2(v.x - hx, v.y - hy), pack_h2(v.z - hz, v.w - hw));
            }
            *reinterpret_cast<uint4*>(&n[OFF_BH + be * SB2 + 8 * bs]) = pbh;
            *reinterpret_cast<uint4*>(&n[OFF_BL + be * SB2 + 8 * bs]) = pbl;
        }
        __syncthreads();
    }

    // ---- epilogue: logits -> smem [128][65] floats, then top-2 per token ----
    float* slog = reinterpret_cast<float*>(stg);
#pragma unroll
    for (int i = 0; i < 2; i++) {
        const int r0 = w * 32 + i * 16 + g;
#pragma unroll
        for (int j = 0; j < 8; j++) {
            const int col = j * 8 + 2 * c;
            slog[r0 * 65 + col]           = acc[i][j][0] + sbias[col];
            slog[r0 * 65 + col + 1]       = acc[i][j][1] + sbias[col + 1];
            slog[(r0 + 8) * 65 + col]     = acc[i][j][2] + sbias[col];
            slog[(r0 + 8) * 65 + col + 1] = acc[i][j][3] + sbias[col + 1];
        }
    }
    __syncthreads();

    {
        const int t = tid;
        float best = -INFINITY, second = -INFINITY;
        int bi = 0, si = 0;
#pragma unroll 8
        for (int e = 0; e < EQ; e++) {
            float v = slog[t * 65 + e];
            if (v > best)        { second = best; si = bi; best = v; bi = e; }
            else if (v > second) { second = v; si = e; }
        }
        float es  = expf(second - best);
        float inv = 1.f / (1.f + es);
        int gt = tok0 + t;
        out_idx[gt * 2 + 0] = (float)bi;
        out_idx[gt * 2 + 1] = (float)si;
        out_w[gt * 2 + 0]   = inv;
        out_w[gt * 2 + 1]   = es * inv;
    }

    if (blockIdx.x == 0 && tid == 0 && aux_ptr != nullptr) *aux_ptr = 64.0f;
}

// ---------------------------------------------------------------------------
extern "C" void kernel_launch(void* const* d_in, const int* in_sizes, int n_in,
                              void* d_out, int out_size) {
    const float* input = (const float*)d_in[0];
    const float* W_hid = (const float*)d_in[1];
    const float* b_hid = (const float*)d_in[2];
    const float* W_exp = (const float*)d_in[3];
    const float* b_exp = (const float*)d_in[4];
    const float* emb   = (const float*)d_in[5];

    float* out     = (float*)d_out;
    float* out_idx = out;
    float* out_w   = out + 2 * TQ;
    float* aux     = (out_size > 4 * TQ) ? (out + (out_size - 1)) : nullptr;

    cudaFuncSetAttribute(k3_mma, cudaFuncAttributeMaxDynamicSharedMemorySize, K3_SMEM_BYTES);

    k1_remb<<<EQ, 256>>>(W_exp, b_exp, emb, b_hid);
    k2_part<<<dim3(DQ / 64, 8), 256>>>(W_hid);
    k2_reduce<<<(EQ * DQ / 4) / 256, 256>>>();
    k3_mma<<<TQ / 128, 128, K3_SMEM_BYTES>>>(input, out_idx, out_w, aux);
}

// round 9
// speedup vs baseline: 4.6124x; 1.2710x over previous
#include <cuda_runtime.h>
#include <cuda_fp16.h>
#include <math.h>
#include <stdint.h>

// Problem dims
#define DQ    2048
#define RQ    1024
#define MQ    128
#define EQ    64
#define TQ    32768
#define PADA  68

// k3 tiling (fp16 x3, m16n8k16), cp.async 3-stage pipeline
#define KC        16
#define NST       3
#define SAF       24                     // floats per staged A row (16+8) -> all-32-bank LDS.64
#define SBH       24                     // halfs per staged B row
#define A_BYTES   (128 * SAF * 4)        // 12288
#define BH_OFF    A_BYTES                // 12288
#define BL_OFF    (A_BYTES + 64 * SBH * 2)   // 15360
#define ST_BYTES  (A_BYTES + 2 * 64 * SBH * 2)   // 18432
#define K3_SMEM_BYTES (256 + NST * ST_BYTES)     // 55552

// ---------------- scratch ----------------
__device__ float  g_remb[EQ * RQ];
__device__ float  g_rembT[RQ * EQ];
__device__ float  g_partialT[8][EQ * DQ];   // [e][d] fp32
__device__ __half g_BhT[EQ * DQ];           // fp16-hi of W_combT [e][d]
__device__ __half g_BlT[EQ * DQ];           // fp16-lo
__device__ float  g_biasP[4][EQ];
__device__ float  g_bias[EQ];

__device__ __forceinline__ float mask11(float x) {   // keep 11 significand bits (fp16-exact)
    return __uint_as_float(__float_as_uint(x) & 0xFFFFE000u);
}
__device__ __forceinline__ uint32_t pack_h2(float lo, float hi) {
    __half2 h = __floats2half2_rn(lo, hi);
    return *reinterpret_cast<uint32_t*>(&h);
}
__device__ __forceinline__ uint32_t smem_u32(const void* p) {
    uint32_t a;
    asm("{ .reg .u64 t; cvta.to.shared.u64 t, %1; cvt.u32.u64 %0, t; }" : "=r"(a) : "l"(p));
    return a;
}
__device__ __forceinline__ void cpa16(uint32_t s, const void* g) {
    asm volatile("cp.async.cg.shared.global [%0], [%1], 16;" :: "r"(s), "l"(g));
}
#define CPA_COMMIT() asm volatile("cp.async.commit_group;" ::: "memory")
#define CPA_WAIT1()  asm volatile("cp.async.wait_group 1;" ::: "memory")
#define CPA_WAIT0()  asm volatile("cp.async.wait_group 0;" ::: "memory")

// m16n8k16 fp16 mma, f32 accum, D += A*B (row.col)
__device__ __forceinline__ void mma16(float* d, const uint32_t* a, uint32_t b0, uint32_t b1) {
    asm volatile(
        "mma.sync.aligned.m16n8k16.row.col.f32.f16.f16.f32 "
        "{%0,%1,%2,%3}, {%4,%5,%6,%7}, {%8,%9}, {%0,%1,%2,%3};"
        : "+f"(d[0]), "+f"(d[1]), "+f"(d[2]), "+f"(d[3])
        : "r"(a[0]), "r"(a[1]), "r"(a[2]), "r"(a[3]), "r"(b0), "r"(b1));
}

// ---------------------------------------------------------------------------
// K1: rkhs_emb[e][r] = sum_m emb[e][m]*W_exp[r][m] + b_exp[r], grid (EQ, 4).
// Quarter q covers r in [q*256, q*256+256); warp w -> 32 r's. Bias partials
// per quarter (deterministically reduced in k2_reduce).
// ---------------------------------------------------------------------------
__global__ void k1_remb(const float* __restrict__ W_exp,
                        const float* __restrict__ b_exp,
                        const float* __restrict__ emb,
                        const float* __restrict__ b_hid) {
    __shared__ float4 s_emb[MQ / 4];
    __shared__ float  red[8];
    const int e    = blockIdx.x;
    const int q    = blockIdx.y;
    const int tid  = threadIdx.x;
    const int w    = tid >> 5;
    const int lane = tid & 31;
    if (tid < MQ / 4) s_emb[tid] = reinterpret_cast<const float4*>(emb)[e * (MQ / 4) + tid];
    __syncthreads();
    const float4 ev = s_emb[lane];
    float bacc = 0.f;
#pragma unroll 4
    for (int i = 0; i < 32; i++) {
        const int r = q * 256 + w * 32 + i;
        float4 wv = reinterpret_cast<const float4*>(W_exp)[r * (MQ / 4) + lane];
        float p = wv.x * ev.x + wv.y * ev.y + wv.z * ev.z + wv.w * ev.w;
        p += __shfl_xor_sync(0xffffffffu, p, 16);
        p += __shfl_xor_sync(0xffffffffu, p, 8);
        p += __shfl_xor_sync(0xffffffffu, p, 4);
        p += __shfl_xor_sync(0xffffffffu, p, 2);
        p += __shfl_xor_sync(0xffffffffu, p, 1);
        if (lane == 0) {
            float v = p + b_exp[r];
            g_remb[e * RQ + r]  = v;
            g_rembT[r * EQ + e] = v;
            bacc += b_hid[r] * v;
        }
    }
    if (lane == 0) red[w] = bacc;
    __syncthreads();
    if (tid == 0) {
        float s = 0.f;
#pragma unroll
        for (int i = 0; i < 8; i++) s += red[i];
        g_biasP[q][e] = s;
    }
}

// ---------------------------------------------------------------------------
// K2: split-K GEMM -> partials of W_combT[e][d]
// ---------------------------------------------------------------------------
__global__ __launch_bounds__(256) void k2_part(const float* __restrict__ W_hid) {
    __shared__ float sW[16 * PADA];
    __shared__ float sR[16 * 64];
    const int tid = threadIdx.x;
    const int d0  = blockIdx.x * 64;
    const int r0  = blockIdx.y * 128;
    const int tm  = tid >> 4;
    const int tn  = tid & 15;
    const int rr  = tid >> 4;
    const int dq  = tid & 15;

    float acc[4][4];
#pragma unroll
    for (int i = 0; i < 4; i++)
#pragma unroll
        for (int j = 0; j < 4; j++) acc[i][j] = 0.f;

    const float4* RT4 = reinterpret_cast<const float4*>(g_rembT);

    for (int rk = 0; rk < 128; rk += 16) {
        *reinterpret_cast<float4*>(&sW[rr * PADA + dq * 4]) =
            *reinterpret_cast<const float4*>(&W_hid[(size_t)(r0 + rk + rr) * DQ + d0 + dq * 4]);
        *reinterpret_cast<float4*>(&sR[tid * 4]) = RT4[(size_t)(r0 + rk) * (EQ / 4) + tid];
        __syncthreads();
#pragma unroll
        for (int k = 0; k < 16; k++) {
            float4 a = *reinterpret_cast<const float4*>(&sW[k * PADA + tm * 4]);
            float4 b = *reinterpret_cast<const float4*>(&sR[k * 64 + tn * 4]);
            acc[0][0] += a.x * b.x; acc[0][1] += a.x * b.y; acc[0][2] += a.x * b.z; acc[0][3] += a.x * b.w;
            acc[1][0] += a.y * b.x; acc[1][1] += a.y * b.y; acc[1][2] += a.y * b.z; acc[1][3] += a.y * b.w;
            acc[2][0] += a.z * b.x; acc[2][1] += a.z * b.y; acc[2][2] += a.z * b.z; acc[2][3] += a.z * b.w;
            acc[3][0] += a.w * b.x; acc[3][1] += a.w * b.y; acc[3][2] += a.w * b.z; acc[3][3] += a.w * b.w;
        }
        __syncthreads();
    }
    float* dst = &g_partialT[blockIdx.y][0];
#pragma unroll
    for (int i = 0; i < 4; i++)
#pragma unroll
        for (int j = 0; j < 4; j++)
            dst[(size_t)(tn * 4 + j) * DQ + d0 + tm * 4 + i] = acc[i][j];
}

// K2r: reduce partials -> fp16 hi/lo; block 0 also reduces bias partials.
__global__ void k2_reduce() {
    const int i = blockIdx.x * 256 + threadIdx.x;   // float4 index over EQ*DQ
    float4 s = make_float4(0.f, 0.f, 0.f, 0.f);
#pragma unroll
    for (int p = 0; p < 8; p++) {
        float4 v = reinterpret_cast<const float4*>(&g_partialT[p][0])[i];
        s.x += v.x; s.y += v.y; s.z += v.z; s.w += v.w;
    }
    float hx = mask11(s.x), hy = mask11(s.y), hz = mask11(s.z), hw = mask11(s.w);
    reinterpret_cast<uint2*>(g_BhT)[i] = make_uint2(pack_h2(hx, hy), pack_h2(hz, hw));
    reinterpret_cast<uint2*>(g_BlT)[i] = make_uint2(pack_h2(s.x - hx, s.y - hy),
                                                   pack_h2(s.z - hz, s.w - hw));
    if (blockIdx.x == 0 && threadIdx.x < EQ) {
        const int e = threadIdx.x;
        g_bias[e] = (g_biasP[0][e] + g_biasP[1][e]) + (g_biasP[2][e] + g_biasP[3][e]);
    }
}

// ---------------------------------------------------------------------------
// K3: fp16x3 mma.sync GEMM [128 tok x 64 exp x 2048] + fused top-2.
// cp.async 3-stage ring; A staged fp32 (split to fp16 hi/lo in registers).
// ---------------------------------------------------------------------------
__global__ __launch_bounds__(128, 3) void k3_mma(const float* __restrict__ input,
                                                 float* __restrict__ out_idx,
                                                 float* __restrict__ out_w,
                                                 float* __restrict__ aux_ptr) {
    extern __shared__ char smc[];
    float* sbias = reinterpret_cast<float*>(smc);    // [0,64) floats
    char*  stg   = smc + 256;
    const int tid  = threadIdx.x;
    const int w    = tid >> 5;
    const int lane = tid & 31;
    const int g    = lane >> 2;
    const int c    = lane & 3;
    const int tok0 = blockIdx.x * 128;

    if (tid < EQ) sbias[tid] = g_bias[tid];

    float acc[2][8][4];
#pragma unroll
    for (int i = 0; i < 2; i++)
#pragma unroll
        for (int j = 0; j < 8; j++)
#pragma unroll
            for (int q2 = 0; q2 < 4; q2++) acc[i][j][q2] = 0.f;

    // staging coords
    const int arow = tid >> 2, aj = tid & 3;          // A: 4 rows/thread (row+32u), 16B col aj
    const int be = tid >> 1, bs = tid & 1;            // B: expert be, 16B seg bs

    const uint32_t stg_u = smem_u32(stg);

    // issue stage for chunk ch into slot
    auto issue = [&](int ch, int slot) {
        const uint32_t st = stg_u + slot * ST_BYTES;
        const int k0 = ch * KC;
#pragma unroll
        for (int u = 0; u < 4; u++) {
            int row = arow + 32 * u;
            cpa16(st + row * (SAF * 4) + aj * 16,
                  input + (size_t)(tok0 + row) * DQ + k0 + aj * 4);
        }
        cpa16(st + BH_OFF + be * (SBH * 2) + bs * 16, g_BhT + (size_t)be * DQ + k0 + bs * 8);
        cpa16(st + BL_OFF + be * (SBH * 2) + bs * 16, g_BlT + (size_t)be * DQ + k0 + bs * 8);
    };

    issue(0, 0); CPA_COMMIT();
    issue(1, 1); CPA_COMMIT();

    int slot = 0;
    for (int ch = 0; ch < DQ / KC; ch++) {
        CPA_WAIT1();
        __syncthreads();

        const char* st = stg + slot * ST_BYTES;
        const float*  Af = reinterpret_cast<const float*>(st);
        const __half* Bh = reinterpret_cast<const __half*>(st + BH_OFF);
        const __half* Bl = reinterpret_cast<const __half*>(st + BL_OFF);

        // A fragments: LDS.64 fp32 pairs -> split hi/lo in registers
        uint32_t ahf[2][4], alf[2][4];
#pragma unroll
        for (int i = 0; i < 2; i++) {
            const int rb = w * 32 + i * 16 + g;
#pragma unroll
            for (int q2 = 0; q2 < 4; q2++) {
                const int row = (q2 & 1) ? rb + 8 : rb;
                const int kk  = 2 * c + ((q2 >> 1) ? 8 : 0);
                float2 v = *reinterpret_cast<const float2*>(&Af[row * SAF + kk]);
                float hx = mask11(v.x), hy = mask11(v.y);
                ahf[i][q2] = pack_h2(hx, hy);
                alf[i][q2] = pack_h2(v.x - hx, v.y - hy);
            }
        }

        // pass 1: hi*hi — cache Bh fragments for pass 3
        uint32_t bhf[8][2];
#pragma unroll
        for (int j = 0; j < 8; j++) {
            const int e = j * 8 + g;
            bhf[j][0] = *reinterpret_cast<const uint32_t*>(&Bh[e * SBH + 2 * c]);
            bhf[j][1] = *reinterpret_cast<const uint32_t*>(&Bh[e * SBH + 2 * c + 8]);
            mma16(acc[0][j], ahf[0], bhf[j][0], bhf[j][1]);
            mma16(acc[1][j], ahf[1], bhf[j][0], bhf[j][1]);
        }
        // pass 2: hi*lo
#pragma unroll
        for (int j = 0; j < 8; j++) {
            const int e = j * 8 + g;
            uint32_t b0 = *reinterpret_cast<const uint32_t*>(&Bl[e * SBH + 2 * c]);
            uint32_t b1 = *reinterpret_cast<const uint32_t*>(&Bl[e * SBH + 2 * c + 8]);
            mma16(acc[0][j], ahf[0], b0, b1);
            mma16(acc[1][j], ahf[1], b0, b1);
        }
        // pass 3: lo*hi (reuse cached Bh)
#pragma unroll
        for (int j = 0; j < 8; j++) {
            mma16(acc[0][j], alf[0], bhf[j][0], bhf[j][1]);
            mma16(acc[1][j], alf[1], bhf[j][0], bhf[j][1]);
        }

        // prefetch chunk ch+2 into the slot chunk ch-1 used (all warps past it)
        if (ch + 2 < DQ / KC) {
            int ns = slot + 2; if (ns >= NST) ns -= NST;
            issue(ch + 2, ns);
        }
        CPA_COMMIT();

        if (++slot == NST) slot = 0;
    }
    CPA_WAIT0();
    __syncthreads();

    // ---- epilogue: logits -> smem [128][65] floats, then top-2 per token ----
    float* slog = reinterpret_cast<float*>(stg);
#pragma unroll
    for (int i = 0; i < 2; i++) {
        const int r0 = w * 32 + i * 16 + g;
#pragma unroll
        for (int j = 0; j < 8; j++) {
            const int col = j * 8 + 2 * c;
            slog[r0 * 65 + col]           = acc[i][j][0] + sbias[col];
            slog[r0 * 65 + col + 1]       = acc[i][j][1] + sbias[col + 1];
            slog[(r0 + 8) * 65 + col]     = acc[i][j][2] + sbias[col];
            slog[(r0 + 8) * 65 + col + 1] = acc[i][j][3] + sbias[col + 1];
        }
    }
    __syncthreads();

    {
        const int t = tid;
        float best = -INFINITY, second = -INFINITY;
        int bi = 0, si = 0;
#pragma unroll 8
        for (int e = 0; e < EQ; e++) {
            float v = slog[t * 65 + e];
            if (v > best)        { second = best; si = bi; best = v; bi = e; }
            else if (v > second) { second = v; si = e; }
        }
        float es  = expf(second - best);
        float inv = 1.f / (1.f + es);
        int gt = tok0 + t;
        out_idx[gt * 2 + 0] = (float)bi;
        out_idx[gt * 2 + 1] = (float)si;
        out_w[gt * 2 + 0]   = inv;
        out_w[gt * 2 + 1]   = es * inv;
    }

    if (blockIdx.x == 0 && tid == 0 && aux_ptr != nullptr) *aux_ptr = 64.0f;
}

// ---------------------------------------------------------------------------
extern "C" void kernel_launch(void* const* d_in, const int* in_sizes, int n_in,
                              void* d_out, int out_size) {
    const float* input = (const float*)d_in[0];
    const float* W_hid = (const float*)d_in[1];
    const float* b_hid = (const float*)d_in[2];
    const float* W_exp = (const float*)d_in[3];
    const float* b_exp = (const float*)d_in[4];
    const float* emb   = (const float*)d_in[5];

    float* out     = (float*)d_out;
    float* out_idx = out;
    float* out_w   = out + 2 * TQ;
    float* aux     = (out_size > 4 * TQ) ? (out + (out_size - 1)) : nullptr;

    cudaFuncSetAttribute(k3_mma, cudaFuncAttributeMaxDynamicSharedMemorySize, K3_SMEM_BYTES);

    k1_remb<<<dim3(EQ, 4), 256>>>(W_exp, b_exp, emb, b_hid);
    k2_part<<<dim3(DQ / 64, 8), 256>>>(W_hid);
    k2_reduce<<<(EQ * DQ / 4) / 256, 256>>>();
    k3_mma<<<TQ / 128, 128, K3_SMEM_BYTES>>>(input, out_idx, out_w, aux);
}